// round 2
// baseline (speedup 1.0000x reference)
#include <cuda_runtime.h>
#include <cstdint>

// ---------------------------------------------------------------------------
// Exact integer replication of the reference gate-level fp32 adder circuit.
// Input/output words are in standard IEEE layout:
//   bit 31 = sign, bits [30:23] = exponent (MSB-first), bits [22:0] = mantissa.
// NOTE: deliberately matches the circuit, NOT IEEE (subnormal results are
// truncated, subnormal mantissa path takes top 23 bits of mant_res unshifted,
// big-diff threshold is ediff>=24, exact cancel -> +0, etc.)
// ---------------------------------------------------------------------------
__device__ __forceinline__ uint32_t fpadd_circuit(uint32_t ua, uint32_t ub) {
    uint32_t sa = ua >> 31, sb = ub >> 31;
    uint32_t ea = (ua >> 23) & 0xFFu, eb = (ub >> 23) & 0xFFu;
    uint32_t ma = ua & 0x7FFFFFu, mb = ub & 0x7FFFFFu;

    uint32_t ha = (ea != 0u) ? 1u : 0u;
    uint32_t hb = (eb != 0u) ? 1u : 0u;
    uint32_t eaf = ha ? ea : 1u;           // effective exponent (subnormal -> 1)
    uint32_t ebf = hb ? eb : 1u;

    uint32_t Ma = (ha << 27) | (ma << 4);  // 28-bit mantissa: hidden|m|0000
    uint32_t Mb = (hb << 27) | (mb << 4);
    uint32_t maga = (ha << 23) | ma;       // 24-bit magnitude compare operand
    uint32_t magb = (hb << 23) | mb;

    bool exp_eq = (eaf == ebf);
    bool a_ge_b = (eaf > ebf) || (exp_eq && (maga >= magb));
    bool abs_eq = exp_eq && (maga == magb);

    uint32_t ediff = a_ge_b ? (eaf - ebf) : (ebf - eaf);
    bool big = (ediff >= 24u);

    uint32_t e_max  = a_ge_b ? eaf : ebf;
    uint32_t Ml     = a_ge_b ? Ma  : Mb;
    uint32_t Ms0    = a_ge_b ? Mb  : Ma;

    uint32_t Ms;
    bool shift_sticky;
    if (big) {
        Ms = 0u;
        shift_sticky = (Ms0 != 0u);
    } else {
        Ms = Ms0 >> ediff;
        shift_sticky = (Ms0 & ((1u << ediff) - 1u)) != 0u;  // ediff==0 -> mask 0
    }

    bool dsign = (sa != sb);
    uint32_t s_large = a_ge_b ? sa : sb;

    uint32_t mant_res, carry;
    if (dsign) {
        mant_res = (Ml - Ms - (shift_sticky ? 1u : 0u)) & 0x0FFFFFFFu;
        carry = 0u;
    } else {
        uint32_t s = Ml + Ms;
        carry = s >> 28;
        mant_res = s & 0x0FFFFFFFu;
    }

    uint32_t lzc = mant_res ? (uint32_t)(__clz(mant_res) - 4) : 28u;  // 0..28
    bool underflow = (lzc >= e_max);
    uint32_t norm = (mant_res << lzc) & 0x0FFFFFFFu;   // lzc<=27 when nonzero

    uint32_t e_after = (e_max - lzc) & 0xFFu;          // 8-bit wrap like circuit
    uint32_t e_normal = underflow ? 0u : e_after;
    uint32_t final_e_pre = carry ? ((e_max + 1u) & 0xFFu) : e_normal;

    uint32_t m_pre, r_pre;
    bool st_pre;
    if (carry) {
        m_pre  = mant_res >> 5;              // bits 0..22 (MSB-first)
        r_pre  = (mant_res >> 4) & 1u;       // bit 23
        st_pre = (mant_res & 0xFu) != 0u;    // bits 24..27
    } else {
        m_pre  = (norm >> 4) & 0x7FFFFFu;    // bits 1..23
        r_pre  = (norm >> 3) & 1u;           // bit 24
        st_pre = (norm & 0x7u) != 0u;        // bits 25..27
    }
    st_pre = st_pre || shift_sticky;

    uint32_t m_sel = underflow ? (mant_res >> 5) : m_pre;  // subnormal: top 23 bits, unshifted
    bool do_round = (r_pre != 0u) && (st_pre || ((m_sel & 1u) != 0u)) && !underflow;

    uint32_t m24 = m_sel + (do_round ? 1u : 0u);
    uint32_t rc = (m24 >> 23) & 1u;
    uint32_t m_final = m24 & 0x7FFFFFu;
    uint32_t computed_e = (final_e_pre + rc) & 0xFFu;

    bool cancel = dsign && abs_eq;            // exact cancellation -> +0
    uint32_t out_s = cancel ? 0u : s_large;
    uint32_t out_e = cancel ? 0u : computed_e;
    uint32_t out_m = cancel ? 0u : m_final;

    bool ea1 = (ea == 0xFFu), eb1 = (eb == 0xFFu);
    bool manz = (ma != 0u),   mbnz = (mb != 0u);
    bool a_inf = ea1 && !manz, b_inf = eb1 && !mbnz;
    bool any_nan = (ea1 && manz) || (eb1 && mbnz);
    bool res_nan = any_nan || (dsign && a_inf && b_inf);
    bool ovf = (computed_e == 0xFFu);         // on computed_e, pre-cancel (as circuit)

    uint32_t out = (out_s << 31) | (out_e << 23) | out_m;
    if (a_inf || b_inf || ovf) out = (s_large << 31) | 0x7F800000u;
    if (res_nan)               out = 0x7FFFFFFFu;
    return out;
}

// Each warp processes 32 rows. One coalesced 128B load per row per input;
// ballot packs the row bits into a word; brev puts it in IEEE layout.
__global__ void __launch_bounds__(256)
spike_fp32_adder_kernel(const float* __restrict__ A,
                        const float* __restrict__ B,
                        uint32_t* __restrict__ O,
                        int nrows) {
    const unsigned FULL = 0xFFFFFFFFu;
    const int lane = threadIdx.x & 31;
    const int warp = blockIdx.x * (blockDim.x >> 5) + (threadIdx.x >> 5);
    const int row0 = warp << 5;       // 32 rows per warp
    if (row0 >= nrows) return;
    const int nv = min(32, nrows - row0);   // warp-uniform

    const float* Ab = A + (size_t)row0 * 32;
    const float* Bb = B + (size_t)row0 * 32;
    uint32_t* Ob = O + (size_t)row0 * 32;

    uint32_t ua = 0u, ub = 0u;
    #pragma unroll
    for (int r = 0; r < 32; ++r) {
        if (r >= nv) break;                         // warp-uniform
        uint32_t wa = __ballot_sync(FULL, Ab[r * 32 + lane] != 0.0f);
        uint32_t wb = __ballot_sync(FULL, Bb[r * 32 + lane] != 0.0f);
        if (lane == r) { ua = wa; ub = wb; }
    }

    // ballot word: bit i (LSB=lane0) == logical bit i (MSB-first encoding)
    // -> brev gives standard IEEE layout
    uint32_t res = fpadd_circuit(__brev(ua), __brev(ub));
    res = __brev(res);   // back to "bit i of word = logical bit i"

    #pragma unroll
    for (int r = 0; r < 32; ++r) {
        if (r >= nv) break;                         // warp-uniform
        uint32_t w = __shfl_sync(FULL, res, r);
        Ob[r * 32 + lane] = ((w >> lane) & 1u) ? 0x3F800000u : 0u;  // 1.0f / 0.0f
    }
}

extern "C" void kernel_launch(void* const* d_in, const int* in_sizes, int n_in,
                              void* d_out, int out_size) {
    const float* A = (const float*)d_in[0];
    const float* B = (const float*)d_in[1];
    uint32_t* O = (uint32_t*)d_out;

    int nrows = in_sizes[0] / 32;                  // 524288
    int warps = (nrows + 31) / 32;                 // 16384
    int threads = 256;                             // 8 warps/block
    int wpb = threads / 32;
    int blocks = (warps + wpb - 1) / wpb;          // 2048

    spike_fp32_adder_kernel<<<blocks, threads>>>(A, B, O, nrows);
}

// round 3
// speedup vs baseline: 2.2212x; 2.2212x over previous
#include <cuda_runtime.h>
#include <cstdint>

// ---------------------------------------------------------------------------
// Exact integer replication of the reference gate-level fp32 adder circuit.
// Words are in standard IEEE layout: bit31=sign, [30:23]=exp, [22:0]=mant.
// Deliberately matches the circuit, NOT IEEE (truncated subnormal results,
// subnormal mantissa path takes top 23 bits unshifted, big-diff at ediff>=24,
// exact cancel -> +0, overflow checked on computed_e pre-cancel, etc.)
// ---------------------------------------------------------------------------
__device__ __forceinline__ uint32_t fpadd_circuit(uint32_t ua, uint32_t ub) {
    uint32_t sa = ua >> 31, sb = ub >> 31;
    uint32_t ea = (ua >> 23) & 0xFFu, eb = (ub >> 23) & 0xFFu;
    uint32_t ma = ua & 0x7FFFFFu, mb = ub & 0x7FFFFFu;

    uint32_t ha = (ea != 0u) ? 1u : 0u;
    uint32_t hb = (eb != 0u) ? 1u : 0u;
    uint32_t eaf = ha ? ea : 1u;
    uint32_t ebf = hb ? eb : 1u;

    uint32_t Ma = (ha << 27) | (ma << 4);
    uint32_t Mb = (hb << 27) | (mb << 4);
    uint32_t maga = (ha << 23) | ma;
    uint32_t magb = (hb << 23) | mb;

    bool exp_eq = (eaf == ebf);
    bool a_ge_b = (eaf > ebf) || (exp_eq && (maga >= magb));
    bool abs_eq = exp_eq && (maga == magb);

    uint32_t ediff = a_ge_b ? (eaf - ebf) : (ebf - eaf);
    bool big = (ediff >= 24u);

    uint32_t e_max  = a_ge_b ? eaf : ebf;
    uint32_t Ml     = a_ge_b ? Ma  : Mb;
    uint32_t Ms0    = a_ge_b ? Mb  : Ma;

    uint32_t Ms;
    bool shift_sticky;
    if (big) {
        Ms = 0u;
        shift_sticky = (Ms0 != 0u);
    } else {
        Ms = Ms0 >> ediff;
        shift_sticky = (Ms0 & ((1u << ediff) - 1u)) != 0u;
    }

    bool dsign = (sa != sb);
    uint32_t s_large = a_ge_b ? sa : sb;

    uint32_t mant_res, carry;
    if (dsign) {
        mant_res = (Ml - Ms - (shift_sticky ? 1u : 0u)) & 0x0FFFFFFFu;
        carry = 0u;
    } else {
        uint32_t s = Ml + Ms;
        carry = s >> 28;
        mant_res = s & 0x0FFFFFFFu;
    }

    uint32_t lzc = mant_res ? (uint32_t)(__clz(mant_res) - 4) : 28u;
    bool underflow = (lzc >= e_max);
    uint32_t norm = (mant_res << lzc) & 0x0FFFFFFFu;

    uint32_t e_after = (e_max - lzc) & 0xFFu;
    uint32_t e_normal = underflow ? 0u : e_after;
    uint32_t final_e_pre = carry ? ((e_max + 1u) & 0xFFu) : e_normal;

    uint32_t m_pre, r_pre;
    bool st_pre;
    if (carry) {
        m_pre  = mant_res >> 5;
        r_pre  = (mant_res >> 4) & 1u;
        st_pre = (mant_res & 0xFu) != 0u;
    } else {
        m_pre  = (norm >> 4) & 0x7FFFFFu;
        r_pre  = (norm >> 3) & 1u;
        st_pre = (norm & 0x7u) != 0u;
    }
    st_pre = st_pre || shift_sticky;

    uint32_t m_sel = underflow ? (mant_res >> 5) : m_pre;
    bool do_round = (r_pre != 0u) && (st_pre || ((m_sel & 1u) != 0u)) && !underflow;

    uint32_t m24 = m_sel + (do_round ? 1u : 0u);
    uint32_t rc = (m24 >> 23) & 1u;
    uint32_t m_final = m24 & 0x7FFFFFu;
    uint32_t computed_e = (final_e_pre + rc) & 0xFFu;

    bool cancel = dsign && abs_eq;
    uint32_t out_s = cancel ? 0u : s_large;
    uint32_t out_e = cancel ? 0u : computed_e;
    uint32_t out_m = cancel ? 0u : m_final;

    bool ea1 = (ea == 0xFFu), eb1 = (eb == 0xFFu);
    bool manz = (ma != 0u),   mbnz = (mb != 0u);
    bool a_inf = ea1 && !manz, b_inf = eb1 && !mbnz;
    bool any_nan = (ea1 && manz) || (eb1 && mbnz);
    bool res_nan = any_nan || (dsign && a_inf && b_inf);
    bool ovf = (computed_e == 0xFFu);

    uint32_t out = (out_s << 31) | (out_e << 23) | out_m;
    if (a_inf || b_inf || ovf) out = (s_large << 31) | 0x7F800000u;
    if (res_nan)               out = 0x7FFFFFFFu;
    return out;
}

#define RPB   256          // rows per block (== threads)
#define SROW  36           // smem bytes per row (32 + 4 pad -> conflict-free LDS)

__global__ void __launch_bounds__(256)
spike_fp32_adder_kernel(const float4* __restrict__ A4,
                        const float4* __restrict__ B4,
                        uint32_t* __restrict__ O,
                        int nrows) {
    __shared__ uint8_t sA[RPB * SROW];
    __shared__ uint8_t sB[RPB * SROW];

    const int tid = threadIdx.x;
    const int row0 = blockIdx.x * RPB;
    if (row0 >= nrows) return;
    const bool full = (row0 + RPB <= nrows);
    const int vlim = (nrows - row0) * 8;          // float4 count in this tile

    // ---- Phase 1: coalesced load, float->bit-byte, store packed to smem ----
    const float4* Af = A4 + (size_t)row0 * 8;     // 8 float4 per row
    const float4* Bf = B4 + (size_t)row0 * 8;
    #pragma unroll
    for (int it = 0; it < 8; ++it) {
        int v = it * RPB + tid;                   // float4 index in tile
        if (!full && v >= vlim) break;
        int base = v << 2;                        // element index
        int row  = base >> 5;
        int col  = base & 31;
        float4 a = Af[v];
        uint32_t pa =  ((__float_as_uint(a.x) >> 29) & 1u)
                    | (((__float_as_uint(a.y) >> 29) & 1u) << 8)
                    | (((__float_as_uint(a.z) >> 29) & 1u) << 16)
                    | (((__float_as_uint(a.w) >> 29) & 1u) << 24);
        *(uint32_t*)(sA + row * SROW + col) = pa;
        float4 b = Bf[v];
        uint32_t pb =  ((__float_as_uint(b.x) >> 29) & 1u)
                    | (((__float_as_uint(b.y) >> 29) & 1u) << 8)
                    | (((__float_as_uint(b.z) >> 29) & 1u) << 16)
                    | (((__float_as_uint(b.w) >> 29) & 1u) << 24);
        *(uint32_t*)(sB + row * SROW + col) = pb;
    }
    __syncthreads();

    // ---- Phase 2: pack own row (MSB-first -> IEEE layout) + circuit ----
    const int myrow = row0 + tid;
    uint32_t res = 0u;
    if (myrow < nrows) {
        uint32_t ua = 0u, ub = 0u;
        #pragma unroll
        for (int j = 0; j < 8; ++j) {
            uint32_t m = *(const uint32_t*)(sA + tid * SROW + (j << 2));
            ua |= (((m * 0x08040201u) >> 24)) << (28 - 4 * j);
            uint32_t n = *(const uint32_t*)(sB + tid * SROW + (j << 2));
            ub |= (((n * 0x08040201u) >> 24)) << (28 - 4 * j);
        }
        res = fpadd_circuit(ua, ub);
    }

    // ---- Phase 3: shfl scatter, coalesced uint4 stores ----
    const int lane  = tid & 31;
    const int wrow0 = row0 + (tid & ~31);         // first row of this warp
    const int sub   = lane >> 3;                  // 0..3 : row within group of 4
    const uint32_t e0 = (lane & 7) << 2;          // element offset within row
    #pragma unroll
    for (int k = 0; k < 8; ++k) {
        int idx  = (k << 2) + sub;                // source lane / row in warp
        uint32_t w = __shfl_sync(0xFFFFFFFFu, res, idx);
        int orow = wrow0 + idx;
        if (full || orow < nrows) {
            uint4 o;
            o.x = (uint32_t)(((int32_t)(w << (e0 + 0))) >> 31) & 0x3F800000u;
            o.y = (uint32_t)(((int32_t)(w << (e0 + 1))) >> 31) & 0x3F800000u;
            o.z = (uint32_t)(((int32_t)(w << (e0 + 2))) >> 31) & 0x3F800000u;
            o.w = (uint32_t)(((int32_t)(w << (e0 + 3))) >> 31) & 0x3F800000u;
            *(uint4*)(O + (size_t)orow * 32 + e0) = o;
        }
    }
}

extern "C" void kernel_launch(void* const* d_in, const int* in_sizes, int n_in,
                              void* d_out, int out_size) {
    const float4* A = (const float4*)d_in[0];
    const float4* B = (const float4*)d_in[1];
    uint32_t* O = (uint32_t*)d_out;

    int nrows  = in_sizes[0] / 32;                // 524288
    int blocks = (nrows + RPB - 1) / RPB;         // 2048

    spike_fp32_adder_kernel<<<blocks, 256>>>(A, B, O, nrows);
}